// round 15
// baseline (speedup 1.0000x reference)
#include <cuda_runtime.h>
#include <cuda_bf16.h>
#include <math.h>
#include <stdint.h>

#define NPIX 16384
#define CDIM 128
#define NB 2
#define NV 6
#define BVI 12
#define WW 128

typedef uint16_t u16;
typedef uint32_t u32;

// ---------------- scratch ----------------
__device__ float g_bufA[(size_t)BVI * CDIM * NPIX];
__device__ float g_bufB[(size_t)BVI * CDIM * NPIX];
__device__ float g_hg  [(size_t)BVI * 2 * CDIM * NPIX];
__device__ float g_alp [(size_t)BVI * NPIX];
__device__ float g_u   [(size_t)NB * CDIM * NPIX];
__device__ __align__(16) u16 g_dwh [(size_t)BVI * CDIM * NPIX], g_dwl [(size_t)BVI * CDIM * NPIX];
__device__ __align__(16) u16 g_m2h [(size_t)BVI * CDIM * NPIX], g_m2l [(size_t)BVI * CDIM * NPIX];
__device__ __align__(16) u16 g_g1h [(size_t)BVI * CDIM * NPIX], g_g1l [(size_t)BVI * CDIM * NPIX];
__device__ __align__(16) u16 g_plh [(size_t)NB * CDIM * NPIX],  g_pll [(size_t)NB * CDIM * NPIX];
__device__ __align__(16) u16 g_wm1h[128 * 256], g_wm1l[128 * 256];
__device__ __align__(16) u16 g_wm2h[128 * 128], g_wm2l[128 * 128];
__device__ __align__(16) u16 g_wgh [256 * 128], g_wgl [256 * 128];
__device__ __align__(16) u16 g_wgbh[256 * 128], g_wgbl[256 * 128];
__device__ __align__(16) u16 g_wuph[128 * 128], g_wupl[128 * 128];

__device__ __forceinline__ float gelu_exact(float x) {
    return 0.5f * x * (1.0f + erff(x * 0.70710678118654752f));
}
__device__ __forceinline__ u32 smem_u32(const void* p) {
    return (u32)__cvta_generic_to_shared(p);
}
__device__ __forceinline__ void split_pack(float v0, float v1, u32& hi, u32& lo) {
    asm("cvt.rn.bf16x2.f32 %0, %1, %2;" : "=r"(hi) : "f"(v1), "f"(v0));
    float r0 = v0 - __uint_as_float(hi << 16);
    float r1 = v1 - __uint_as_float(hi & 0xffff0000u);
    asm("cvt.rn.bf16x2.f32 %0, %1, %2;" : "=r"(lo) : "f"(r1), "f"(r0));
}
__device__ __forceinline__ void ldm_x4(u32* r, u32 addr) {
    asm volatile("ldmatrix.sync.aligned.m8n8.x4.shared.b16 {%0,%1,%2,%3}, [%4];"
                 : "=r"(r[0]), "=r"(r[1]), "=r"(r[2]), "=r"(r[3]) : "r"(addr));
}
__device__ __forceinline__ void ldm_x4t(u32* r, u32 addr) {
    asm volatile("ldmatrix.sync.aligned.m8n8.x4.trans.shared.b16 {%0,%1,%2,%3}, [%4];"
                 : "=r"(r[0]), "=r"(r[1]), "=r"(r[2]), "=r"(r[3]) : "r"(addr));
}
__device__ __forceinline__ void mma_bf16(float* d, const u32* a, const u32* b) {
    asm volatile(
        "mma.sync.aligned.m16n8k16.row.col.f32.bf16.bf16.f32 "
        "{%0,%1,%2,%3}, {%4,%5,%6,%7}, {%8,%9}, {%0,%1,%2,%3};"
        : "+f"(d[0]), "+f"(d[1]), "+f"(d[2]), "+f"(d[3])
        : "r"(a[0]), "r"(a[1]), "r"(a[2]), "r"(a[3]), "r"(b[0]), "r"(b[1]));
}
__device__ __forceinline__ void cpasync16(u32 dst, const void* src) {
    asm volatile("cp.async.cg.shared.global [%0], [%1], 16;" :: "r"(dst), "l"(src));
}
__device__ __forceinline__ void cp_commit() {
    asm volatile("cp.async.commit_group;" ::: "memory");
}

// ---------------- tile constants ----------------
constexpr int KC = 32;
constexpr int A_PITCH_B = 80;
constexpr int A_PLANE_B = 128 * A_PITCH_B;       // 10240
constexpr int A_STAGE_B = 2 * A_PLANE_B;         // 20480
constexpr int BB_PITCH = 272;
constexpr int BB_PLANE = KC * BB_PITCH;          // 8704
constexpr int BB_STAGE = 2 * BB_PLANE;           // 17408
// merge1 (2-stage, register-staged fp32 B)
constexpr int OFF_B0 = 2 * A_STAGE_B;            // 40960
constexpr int GSMEM  = OFF_B0 + 2 * BB_STAGE;    // 75776
// 3-stage ring (plane GEMMs): stage = A hi/lo + B hi/lo
constexpr int ST3    = A_STAGE_B + BB_STAGE;     // 37888
constexpr int GSMEM3 = 3 * ST3;                  // 113664 (x2 CTAs = 222 KB)

// ================= GEMM-F32IN (merge1) =================
template <int KTOT, int MTOT, int EPI, bool SPLIT>
__global__ __launch_bounds__(256, 2) void gemm_mma(
    const float* __restrict__ X0, const float* __restrict__ X1,
    const u16* __restrict__ Wh_g, const u16* __restrict__ Wl_g,
    const float* __restrict__ Bias, const float* __restrict__ Res,
    float* __restrict__ Out)
{
    extern __shared__ __align__(16) char sm[];
    const u32 sm0 = smem_u32(sm);

    const int img = blockIdx.z;
    const int p0  = blockIdx.x * 128;
    const int m0  = blockIdx.y * 128;
    const int tid = threadIdx.x;
    const int lane = tid & 31, wid = tid >> 5;
    const int wm = wid >> 2, wn = wid & 3;

    float acc[4][4][4];
#pragma unroll
    for (int i = 0; i < 4; i++)
#pragma unroll
        for (int j = 0; j < 4; j++)
#pragma unroll
            for (int q = 0; q < 4; q++) acc[i][j][q] = 0.f;

    constexpr int NCH = KTOT / KC;
    float4 breg[2][4];

    auto ldgB = [&](int c, int buf) {
        const int kbase = c * KC;
        const float* Xc = X0;
        int kb = kbase;
        if (SPLIT && kbase >= 128) { Xc = X1; kb = kbase - 128; }
        const size_t bbase = ((size_t)img * (SPLIT ? 128 : KTOT) + kb) * NPIX + p0;
#pragma unroll
        for (int i = 0; i < 4; i++) {
            int idx = tid + i * 256;
            int row = idx >> 5, seg = idx & 31;
            breg[buf][i] = *reinterpret_cast<const float4*>(
                Xc + bbase + (size_t)row * NPIX + seg * 4);
        }
    };
    auto copyA = [&](int c, int s) {
        const size_t abase = (size_t)m0 * KTOT + c * KC;
        const u32 adst = sm0 + s * A_STAGE_B;
#pragma unroll
        for (int i = 0; i < 4; i++) {
            int idx = tid + i * 256;
            int plane = idx >> 9, rem = idx & 511;
            int row = rem >> 2, seg = rem & 3;
            const u16* src = (plane ? Wl_g : Wh_g) + abase + (size_t)row * KTOT + seg * 8;
            cpasync16(adst + plane * A_PLANE_B + row * A_PITCH_B + seg * 16, src);
        }
    };

    const int lr  = lane & 7;
    const int lth = (lane >> 3) & 1;
    const int ltv = lane >> 4;
    const u32 a_row = (u32)(wm * 64 + lth * 8 + lr);

    ldgB(0, 0);
    copyA(0, 0); cp_commit();

#pragma unroll 1
    for (int c = 0; c < NCH; c++) {
        const int s = c & 1;
        if (c + 1 < NCH) ldgB(c + 1, s ^ 1);

        {
            const u32 bhoff = OFF_B0 + s * BB_STAGE;
#pragma unroll
            for (int i = 0; i < 4; i++) {
                int idx = tid + i * 256;
                int row = idx >> 5, seg = idx & 31;
                float4 v = breg[s][i];
                u32 h0, l0, h1, l1;
                split_pack(v.x, v.y, h0, l0);
                split_pack(v.z, v.w, h1, l1);
                u32 off = (u32)row * BB_PITCH + seg * 8;
                *reinterpret_cast<uint2*>(sm + bhoff + off) = make_uint2(h0, h1);
                *reinterpret_cast<uint2*>(sm + bhoff + BB_PLANE + off) = make_uint2(l0, l1);
            }
        }
        asm volatile("cp.async.wait_group 0;" ::: "memory");
        __syncthreads();

        if (c + 1 < NCH) { copyA(c + 1, s ^ 1); cp_commit(); }

        const u32 ah = sm0 + s * A_STAGE_B;
        const u32 al = ah + A_PLANE_B;
        const u32 bh = sm0 + OFF_B0 + s * BB_STAGE;
        const u32 bl = bh + BB_PLANE;

#pragma unroll
        for (int kk = 0; kk < KC / 16; kk++) {
            u32 af[4][4];
            u32 bfh[4][2], bfl[4][2];
            const u32 a_off = a_row * A_PITCH_B + kk * 32 + ltv * 16;
            const u32 b_off = (u32)(kk * 16 + lth * 8 + lr) * BB_PITCH + wn * 64 + ltv * 16;
#pragma unroll
            for (int mf = 0; mf < 4; mf++)
                ldm_x4(af[mf], ah + a_off + mf * 16 * A_PITCH_B);
#pragma unroll
            for (int nh = 0; nh < 2; nh++) {
                u32 r[4];
                ldm_x4t(r, bh + b_off + nh * 32);
                bfh[nh * 2][0] = r[0]; bfh[nh * 2][1] = r[1];
                bfh[nh * 2 + 1][0] = r[2]; bfh[nh * 2 + 1][1] = r[3];
            }
#pragma unroll
            for (int mf = 0; mf < 4; mf++)
#pragma unroll
                for (int nf = 0; nf < 4; nf++)
                    mma_bf16(acc[mf][nf], af[mf], bfh[nf]);
#pragma unroll
            for (int nh = 0; nh < 2; nh++) {
                u32 r[4];
                ldm_x4t(r, bl + b_off + nh * 32);
                bfl[nh * 2][0] = r[0]; bfl[nh * 2][1] = r[1];
                bfl[nh * 2 + 1][0] = r[2]; bfl[nh * 2 + 1][1] = r[3];
            }
#pragma unroll
            for (int mf = 0; mf < 4; mf++)
#pragma unroll
                for (int nf = 0; nf < 4; nf++)
                    mma_bf16(acc[mf][nf], af[mf], bfl[nf]);
#pragma unroll
            for (int mf = 0; mf < 4; mf++)
                ldm_x4(af[mf], al + a_off + mf * 16 * A_PITCH_B);
#pragma unroll
            for (int mf = 0; mf < 4; mf++)
#pragma unroll
                for (int nf = 0; nf < 4; nf++)
                    mma_bf16(acc[mf][nf], af[mf], bfh[nf]);
        }
    }

    const int g = lane >> 2, tg = lane & 3;
#pragma unroll
    for (int mf = 0; mf < 4; mf++) {
#pragma unroll
        for (int half = 0; half < 2; half++) {
            const int m = m0 + wm * 64 + mf * 16 + half * 8 + g;
            const float bias = Bias ? Bias[m] : 0.f;
            const size_t rowb = ((size_t)img * MTOT + m) * NPIX;
#pragma unroll
            for (int nf = 0; nf < 4; nf++) {
                const int px = p0 + wn * 32 + nf * 8 + 2 * tg;
                float v0 = acc[mf][nf][half * 2 + 0] + bias;
                float v1 = acc[mf][nf][half * 2 + 1] + bias;
                if (EPI == 1) { v0 = gelu_exact(v0); v1 = gelu_exact(v1); }
                *reinterpret_cast<float2*>(&Out[rowb + px]) = make_float2(v0, v1);
            }
        }
    }
}

// ================= GEMM-PLANES 3-stage ring (merge2 / GRU / up) ==========
template <int KTOT, int MTOT, int EPI, bool OUTPL>
__global__ __launch_bounds__(256, 2) void gemm_pl3(
    const u16* __restrict__ Bh_g, const u16* __restrict__ Bl_g,
    const u16* __restrict__ Wh_g, const u16* __restrict__ Wl_g,
    const float* __restrict__ Bias, const float* __restrict__ Res,
    u16* __restrict__ OutH, u16* __restrict__ OutL, float* __restrict__ OutF)
{
    extern __shared__ __align__(16) char sm[];
    const u32 sm0 = smem_u32(sm);

    const int img = blockIdx.z;
    const int p0  = blockIdx.x * 128;
    const int m0  = blockIdx.y * 128;
    const int tid = threadIdx.x;
    const int lane = tid & 31, wid = tid >> 5;
    const int wm = wid >> 2, wn = wid & 3;

    float acc[4][4][4];
#pragma unroll
    for (int i = 0; i < 4; i++)
#pragma unroll
        for (int j = 0; j < 4; j++)
#pragma unroll
            for (int q = 0; q < 4; q++) acc[i][j][q] = 0.f;

    constexpr int NCH = KTOT / KC;

    auto copyAB = [&](int c, int s) {
        const int kbase = c * KC;
        const u32 st = sm0 + s * ST3;
        // A planes
        const size_t abase = (size_t)m0 * KTOT + kbase;
#pragma unroll
        for (int i = 0; i < 4; i++) {
            int idx = tid + i * 256;
            int plane = idx >> 9, rem = idx & 511;
            int row = rem >> 2, seg = rem & 3;
            const u16* src = (plane ? Wl_g : Wh_g) + abase + (size_t)row * KTOT + seg * 8;
            cpasync16(st + plane * A_PLANE_B + row * A_PITCH_B + seg * 16, src);
        }
        // B planes
        const size_t bbase = ((size_t)img * KTOT + kbase) * NPIX + p0;
#pragma unroll
        for (int i = 0; i < 4; i++) {
            int idx = tid + i * 256;
            int plane = idx >> 9, rem = idx & 511;
            int row = rem >> 4, seg = rem & 15;
            const u16* src = (plane ? Bl_g : Bh_g) + bbase + (size_t)row * NPIX + seg * 8;
            cpasync16(st + A_STAGE_B + plane * BB_PLANE + row * BB_PITCH + seg * 16, src);
        }
    };

    const int lr  = lane & 7;
    const int lth = (lane >> 3) & 1;
    const int ltv = lane >> 4;
    const u32 a_row = (u32)(wm * 64 + lth * 8 + lr);

    copyAB(0, 0); cp_commit();
    if (NCH > 1) { copyAB(1, 1); cp_commit(); }

#pragma unroll 1
    for (int c = 0; c < NCH; c++) {
        const int s = c % 3;
        if (c + 1 < NCH) {
            asm volatile("cp.async.wait_group 1;" ::: "memory");  // AB(c) landed, AB(c+1) in flight
        } else {
            asm volatile("cp.async.wait_group 0;" ::: "memory");
        }
        __syncthreads();   // MMA(c-1) reads done (stage (c-1)%3 free); stage s visible

        if (c + 2 < NCH) { copyAB(c + 2, (c + 2) % 3); cp_commit(); }  // targets (c-1)%3

        const u32 ah = sm0 + s * ST3;
        const u32 al = ah + A_PLANE_B;
        const u32 bh = ah + A_STAGE_B;
        const u32 bl = bh + BB_PLANE;

#pragma unroll
        for (int kk = 0; kk < KC / 16; kk++) {
            u32 af[4][4];
            u32 bfh[4][2], bfl[4][2];
            const u32 a_off = a_row * A_PITCH_B + kk * 32 + ltv * 16;
            const u32 b_off = (u32)(kk * 16 + lth * 8 + lr) * BB_PITCH + wn * 64 + ltv * 16;
#pragma unroll
            for (int mf = 0; mf < 4; mf++)
                ldm_x4(af[mf], ah + a_off + mf * 16 * A_PITCH_B);
#pragma unroll
            for (int nh = 0; nh < 2; nh++) {
                u32 r[4];
                ldm_x4t(r, bh + b_off + nh * 32);
                bfh[nh * 2][0] = r[0]; bfh[nh * 2][1] = r[1];
                bfh[nh * 2 + 1][0] = r[2]; bfh[nh * 2 + 1][1] = r[3];
            }
#pragma unroll
            for (int mf = 0; mf < 4; mf++)
#pragma unroll
                for (int nf = 0; nf < 4; nf++)
                    mma_bf16(acc[mf][nf], af[mf], bfh[nf]);
#pragma unroll
            for (int nh = 0; nh < 2; nh++) {
                u32 r[4];
                ldm_x4t(r, bl + b_off + nh * 32);
                bfl[nh * 2][0] = r[0]; bfl[nh * 2][1] = r[1];
                bfl[nh * 2 + 1][0] = r[2]; bfl[nh * 2 + 1][1] = r[3];
            }
#pragma unroll
            for (int mf = 0; mf < 4; mf++)
#pragma unroll
                for (int nf = 0; nf < 4; nf++)
                    mma_bf16(acc[mf][nf], af[mf], bfl[nf]);
#pragma unroll
            for (int mf = 0; mf < 4; mf++)
                ldm_x4(af[mf], al + a_off + mf * 16 * A_PITCH_B);
#pragma unroll
            for (int mf = 0; mf < 4; mf++)
#pragma unroll
                for (int nf = 0; nf < 4; nf++)
                    mma_bf16(acc[mf][nf], af[mf], bfh[nf]);
        }
    }

    const int g = lane >> 2, tg = lane & 3;
#pragma unroll
    for (int mf = 0; mf < 4; mf++) {
#pragma unroll
        for (int half = 0; half < 2; half++) {
            const int m = m0 + wm * 64 + mf * 16 + half * 8 + g;
            const float bias = Bias ? Bias[m] : 0.f;
            const size_t rowb = ((size_t)img * MTOT + m) * NPIX;
            const float* resrow = (EPI == 2) ? &Res[((size_t)img * CDIM + m) * NPIX] : nullptr;
#pragma unroll
            for (int nf = 0; nf < 4; nf++) {
                const int px = p0 + wn * 32 + nf * 8 + 2 * tg;
                float v0 = acc[mf][nf][half * 2 + 0] + bias;
                float v1 = acc[mf][nf][half * 2 + 1] + bias;
                if (EPI == 2) { v0 += resrow[px]; v1 += resrow[px + 1]; }
                if (OUTPL) {
                    u32 hi, lo;
                    split_pack(v0, v1, hi, lo);
                    const size_t hw = (rowb + px) >> 1;
                    reinterpret_cast<u32*>(OutH)[hw] = hi;
                    reinterpret_cast<u32*>(OutL)[hw] = lo;
                } else {
                    *reinterpret_cast<float2*>(&OutF[rowb + px]) = make_float2(v0, v1);
                }
            }
        }
    }
}

// ---------------- fused weight prep ----------------
__global__ void prep_w_all(
    const float* __restrict__ w1, const float* __restrict__ w2,
    const float* __restrict__ wg, const float* __restrict__ wgb,
    const float* __restrict__ wup,
    u16* __restrict__ w1h, u16* __restrict__ w1l,
    u16* __restrict__ w2h, u16* __restrict__ w2l,
    u16* __restrict__ wgh, u16* __restrict__ wgl,
    u16* __restrict__ wgbh, u16* __restrict__ wgbl,
    u16* __restrict__ wuph, u16* __restrict__ wupl)
{
    int i = blockIdx.x * 256 + threadIdx.x;
    const float* src; u16 *dh, *dl; int off;
    if      (i < 32768)  { src = w1;  dh = w1h;  dl = w1l;  off = i; }
    else if (i < 49152)  { src = w2;  dh = w2h;  dl = w2l;  off = i - 32768; }
    else if (i < 81920)  { src = wg;  dh = wgh;  dl = wgl;  off = i - 49152; }
    else if (i < 114688) { src = wgb; dh = wgbh; dl = wgbl; off = i - 81920; }
    else                 { src = wup; dh = wuph; dl = wupl; off = i - 114688; }
    float v = src[off];
    float hf = __bfloat162float(__float2bfloat16(v));
    dh[off] = (u16)(__float_as_uint(hf) >> 16);
    dl[off] = (u16)(__float_as_uint(__bfloat162float(__float2bfloat16(v - hf))) >> 16);
}

// ---------------- depthwise 3x3 + bias + GELU: fp32 in, planes out ----------------
__global__ __launch_bounds__(256) void dw3x3_pl(
    const float* __restrict__ in, const float* __restrict__ wd,
    const float* __restrict__ bd, u16* __restrict__ outH, u16* __restrict__ outL)
{
    int c = blockIdx.y, img = blockIdx.z;
    int pix0 = (blockIdx.x * 256 + threadIdx.x) * 2;
    int h = pix0 >> 7, w0 = pix0 & 127;
    const size_t base = ((size_t)img * CDIM + c) * NPIX;
    const float* p = in + base;
    float wreg[9];
#pragma unroll
    for (int i = 0; i < 9; i++) wreg[i] = wd[c * 9 + i];
    float s0 = bd[c], s1 = bd[c];
#pragma unroll
    for (int ky = 0; ky < 3; ky++) {
        int hh = h + ky - 1;
        if ((unsigned)hh >= 128u) continue;
        float v0 = (w0 - 1 >= 0)   ? p[hh * WW + w0 - 1] : 0.f;
        float v1 = p[hh * WW + w0];
        float v2 = p[hh * WW + w0 + 1];
        float v3 = (w0 + 2 < 128)  ? p[hh * WW + w0 + 2] : 0.f;
        s0 = fmaf(wreg[ky * 3 + 0], v0, s0);
        s0 = fmaf(wreg[ky * 3 + 1], v1, s0);
        s0 = fmaf(wreg[ky * 3 + 2], v2, s0);
        s1 = fmaf(wreg[ky * 3 + 0], v1, s1);
        s1 = fmaf(wreg[ky * 3 + 1], v2, s1);
        s1 = fmaf(wreg[ky * 3 + 2], v3, s1);
    }
    u32 hi, lo;
    split_pack(gelu_exact(s0), gelu_exact(s1), hi, lo);
    reinterpret_cast<u32*>(outH)[(base + pix0) >> 1] = hi;
    reinterpret_cast<u32*>(outL)[(base + pix0) >> 1] = lo;
}

// ---------------- minGRU scan (fp32 in, all loads prefetched) ----------------
template <bool OUTPL>
__global__ __launch_bounds__(256) void gru_scan4(
    const float* __restrict__ hg, float* __restrict__ gF,
    u16* __restrict__ gH, u16* __restrict__ gL)
{
    int c = blockIdx.y, b = blockIdx.z;
    int pix0 = (blockIdx.x * 256 + threadIdx.x) * 4;
    float4 hid[NV], gt[NV];
#pragma unroll
    for (int v = 0; v < NV; v++) {
        size_t base = (((size_t)(b * NV + v)) * 2 * CDIM + c) * NPIX + pix0;
        hid[v] = *reinterpret_cast<const float4*>(&hg[base]);
        gt[v]  = *reinterpret_cast<const float4*>(&hg[base + (size_t)CDIM * NPIX]);
    }
    float4 h = make_float4(0.f, 0.f, 0.f, 0.f);
#pragma unroll
    for (int v = 0; v < NV; v++) {
        float z, ht;
        z = 1.f / (1.f + expf(-gt[v].x));
        ht = (hid[v].x >= 0.f) ? (hid[v].x + 0.5f) : (1.f / (1.f + expf(-hid[v].x)));
        h.x = (1.f - z) * h.x + z * ht;
        z = 1.f / (1.f + expf(-gt[v].y));
        ht = (hid[v].y >= 0.f) ? (hid[v].y + 0.5f) : (1.f / (1.f + expf(-hid[v].y)));
        h.y = (1.f - z) * h.y + z * ht;
        z = 1.f / (1.f + expf(-gt[v].z));
        ht = (hid[v].z >= 0.f) ? (hid[v].z + 0.5f) : (1.f / (1.f + expf(-hid[v].z)));
        h.z = (1.f - z) * h.z + z * ht;
        z = 1.f / (1.f + expf(-gt[v].w));
        ht = (hid[v].w >= 0.f) ? (hid[v].w + 0.5f) : (1.f / (1.f + expf(-hid[v].w)));
        h.w = (1.f - z) * h.w + z * ht;
        size_t d = (((size_t)(b * NV + v)) * CDIM + c) * NPIX + pix0;
        if (OUTPL) {
            u32 h0, l0, h1, l1;
            split_pack(h.x, h.y, h0, l0);
            split_pack(h.z, h.w, h1, l1);
            *reinterpret_cast<uint2*>(&gH[d]) = make_uint2(h0, h1);
            *reinterpret_cast<uint2*>(&gL[d]) = make_uint2(l0, l1);
        } else {
            *reinterpret_cast<float4*>(&gF[d]) = h;
        }
    }
}

// ---------------- alpha: 3x3 conv C->1, 2 px/thread ----------------
__global__ __launch_bounds__(256) void alpha_conv2(
    const float* __restrict__ g2, const float* __restrict__ aw,
    const float* __restrict__ ab, float* __restrict__ alpha)
{
    __shared__ float w[1152];
    for (int i = threadIdx.x; i < 1152; i += 256) w[i] = aw[i];
    __syncthreads();
    int img = blockIdx.z;
    int pix0 = (blockIdx.x * 256 + threadIdx.x) * 2;
    int h = pix0 >> 7, x0 = pix0 & 127;
    float s0 = ab[0], s1 = ab[0];
    const float* base = g2 + (size_t)img * CDIM * NPIX;
    for (int c = 0; c < CDIM; c++) {
        const float* p  = base + (size_t)c * NPIX;
        const float* wc = w + c * 9;
#pragma unroll
        for (int ky = 0; ky < 3; ky++) {
            int hh = h + ky - 1;
            if ((unsigned)hh >= 128u) continue;
            float v0 = (x0 - 1 >= 0)  ? p[hh * WW + x0 - 1] : 0.f;
            float v1 = p[hh * WW + x0];
            float v2 = p[hh * WW + x0 + 1];
            float v3 = (x0 + 2 < 128) ? p[hh * WW + x0 + 2] : 0.f;
            s0 = fmaf(wc[ky * 3 + 0], v0, s0);
            s0 = fmaf(wc[ky * 3 + 1], v1, s0);
            s0 = fmaf(wc[ky * 3 + 2], v2, s0);
            s1 = fmaf(wc[ky * 3 + 0], v1, s1);
            s1 = fmaf(wc[ky * 3 + 1], v2, s1);
            s1 = fmaf(wc[ky * 3 + 2], v3, s1);
        }
    }
    *reinterpret_cast<float2*>(&alpha[(size_t)img * NPIX + pix0]) = make_float2(s0, s1);
}

// ---------------- softmax pool (fp32 in, planes out) ----------------
__global__ __launch_bounds__(256) void pool_k4pl(
    const float* __restrict__ g2, const float* __restrict__ alpha,
    u16* __restrict__ outH, u16* __restrict__ outL)
{
    int b = blockIdx.z;
    int pix0 = (blockIdx.x * 256 + threadIdx.x) * 4;
    float4 a[NV];
    float4 mx = make_float4(-1e30f, -1e30f, -1e30f, -1e30f);
#pragma unroll
    for (int v = 0; v < NV; v++) {
        a[v] = *reinterpret_cast<const float4*>(&alpha[(size_t)(b * NV + v) * NPIX + pix0]);
        mx.x = fmaxf(mx.x, a[v].x); mx.y = fmaxf(mx.y, a[v].y);
        mx.z = fmaxf(mx.z, a[v].z); mx.w = fmaxf(mx.w, a[v].w);
    }
    float4 sum = make_float4(0.f, 0.f, 0.f, 0.f);
#pragma unroll
    for (int v = 0; v < NV; v++) {
        a[v].x = expf(a[v].x - mx.x); sum.x += a[v].x;
        a[v].y = expf(a[v].y - mx.y); sum.y += a[v].y;
        a[v].z = expf(a[v].z - mx.z); sum.z += a[v].z;
        a[v].w = expf(a[v].w - mx.w); sum.w += a[v].w;
    }
    float4 inv = make_float4(1.f / sum.x, 1.f / sum.y, 1.f / sum.z, 1.f / sum.w);
#pragma unroll
    for (int v = 0; v < NV; v++) {
        a[v].x *= inv.x; a[v].y *= inv.y; a[v].z *= inv.z; a[v].w *= inv.w;
    }
    for (int c = 0; c < CDIM; c++) {
        float4 s = make_float4(0.f, 0.f, 0.f, 0.f);
#pragma unroll
        for (int v = 0; v < NV; v++) {
            float4 gv = *reinterpret_cast<const float4*>(
                &g2[(((size_t)(b * NV + v)) * CDIM + c) * NPIX + pix0]);
            s.x = fmaf(a[v].x, gv.x, s.x);
            s.y = fmaf(a[v].y, gv.y, s.y);
            s.z = fmaf(a[v].z, gv.z, s.z);
            s.w = fmaf(a[v].w, gv.w, s.w);
        }
        size_t d = ((size_t)b * CDIM + c) * NPIX + pix0;
        u32 h0, l0, h1, l1;
        split_pack(s.x, s.y, h0, l0);
        split_pack(s.z, s.w, h1, l1);
        *reinterpret_cast<uint2*>(&outH[d]) = make_uint2(h0, h1);
        *reinterpret_cast<uint2*>(&outL[d]) = make_uint2(l0, l1);
    }
}

// ---------------- pixel-shuffle(4) + 3x3 conv 8->3 ----------------
__global__ __launch_bounds__(256) void outc_k(
    const float* __restrict__ u, const float* __restrict__ wt,
    const float* __restrict__ bs, float* __restrict__ out)
{
    __shared__ float w[216];
    if (threadIdx.x < 216) w[threadIdx.x] = wt[threadIdx.x];
    __syncthreads();
    int b = blockIdx.z, co = blockIdx.y;
    int idx = blockIdx.x * 256 + threadIdx.x;
    int y = idx >> 9, x = idx & 511;
    float s = bs[co];
    const float* ub = u + (size_t)b * CDIM * NPIX;
#pragma unroll
    for (int ky = 0; ky < 3; ky++) {
        int yy = y + ky - 1;
        if ((unsigned)yy >= 512u) continue;
        int sy = yy & 3, hy = yy >> 2;
#pragma unroll
        for (int kx = 0; kx < 3; kx++) {
            int xx = x + kx - 1;
            if ((unsigned)xx >= 512u) continue;
            int sx = xx & 3, hx = xx >> 2;
            const float* up = ub + (size_t)(sy * 4 + sx) * NPIX + hy * WW + hx;
#pragma unroll
            for (int ci = 0; ci < 8; ci++)
                s = fmaf(w[(co * 8 + ci) * 9 + ky * 3 + kx], up[(size_t)ci * 16 * NPIX], s);
        }
    }
    out[((size_t)b * 3 + co) * (512 * 512) + idx] = s;
}

// ---------------- launch ----------------
extern "C" void kernel_launch(void* const* d_in, const int* in_sizes, int n_in,
                              void* d_out, int out_size)
{
    const float* feats     = (const float*)d_in[0];
    const float* prj       = (const float*)d_in[1];
    const float* merge_w1  = (const float*)d_in[2];
    const float* merge_b1  = (const float*)d_in[3];
    const float* merge_wd  = (const float*)d_in[4];
    const float* merge_bd  = (const float*)d_in[5];
    const float* merge_w2  = (const float*)d_in[6];
    const float* merge_b2  = (const float*)d_in[7];
    const float* gru_w     = (const float*)d_in[8];
    const float* gru_bw    = (const float*)d_in[9];
    const float* alpha_w   = (const float*)d_in[10];
    const float* alpha_b   = (const float*)d_in[11];
    const float* up_w      = (const float*)d_in[12];
    const float* up_b      = (const float*)d_in[13];
    const float* outc_w    = (const float*)d_in[14];
    const float* outc_b    = (const float*)d_in[15];

    float *bufA, *bufB, *hg, *alp, *u;
    u16 *dwh, *dwl, *m2h, *m2l, *g1h, *g1l, *plh, *pll;
    u16 *wm1h, *wm1l, *wm2h, *wm2l, *wgh, *wgl, *wgbh, *wgbl, *wuph, *wupl;
    cudaGetSymbolAddress((void**)&bufA, g_bufA);
    cudaGetSymbolAddress((void**)&bufB, g_bufB);
    cudaGetSymbolAddress((void**)&hg,   g_hg);
    cudaGetSymbolAddress((void**)&alp,  g_alp);
    cudaGetSymbolAddress((void**)&u,    g_u);
    cudaGetSymbolAddress((void**)&dwh,  g_dwh);  cudaGetSymbolAddress((void**)&dwl,  g_dwl);
    cudaGetSymbolAddress((void**)&m2h,  g_m2h);  cudaGetSymbolAddress((void**)&m2l,  g_m2l);
    cudaGetSymbolAddress((void**)&g1h,  g_g1h);  cudaGetSymbolAddress((void**)&g1l,  g_g1l);
    cudaGetSymbolAddress((void**)&plh,  g_plh);  cudaGetSymbolAddress((void**)&pll,  g_pll);
    cudaGetSymbolAddress((void**)&wm1h, g_wm1h); cudaGetSymbolAddress((void**)&wm1l, g_wm1l);
    cudaGetSymbolAddress((void**)&wm2h, g_wm2h); cudaGetSymbolAddress((void**)&wm2l, g_wm2l);
    cudaGetSymbolAddress((void**)&wgh,  g_wgh);  cudaGetSymbolAddress((void**)&wgl,  g_wgl);
    cudaGetSymbolAddress((void**)&wgbh, g_wgbh); cudaGetSymbolAddress((void**)&wgbl, g_wgbl);
    cudaGetSymbolAddress((void**)&wuph, g_wuph); cudaGetSymbolAddress((void**)&wupl, g_wupl);

    cudaFuncSetAttribute(gemm_mma<256, 128, 1, true >, cudaFuncAttributeMaxDynamicSharedMemorySize, GSMEM);
    cudaFuncSetAttribute(gemm_pl3<128, 128, 2, true >, cudaFuncAttributeMaxDynamicSharedMemorySize, GSMEM3);
    cudaFuncSetAttribute(gemm_pl3<128, 256, 0, false>, cudaFuncAttributeMaxDynamicSharedMemorySize, GSMEM3);
    cudaFuncSetAttribute(gemm_pl3<128, 128, 0, false>, cudaFuncAttributeMaxDynamicSharedMemorySize, GSMEM3);

    prep_w_all<<<512, 256>>>(merge_w1, merge_w2, gru_w, gru_bw, up_w,
                             wm1h, wm1l, wm2h, wm2l, wgh, wgl, wgbh, wgbl, wuph, wupl);

    // merge1: 1x1 (2C->C) + GELU (fp32 out)
    gemm_mma<256, 128, 1, true ><<<dim3(128, 1, BVI), 256, GSMEM>>>(
        feats, prj, wm1h, wm1l, merge_b1, nullptr, bufA);
    // depthwise 3x3 + GELU -> planes
    dw3x3_pl<<<dim3(32, CDIM, BVI), 256>>>(bufA, merge_wd, merge_bd, dwh, dwl);
    // merge2: planes in, bias + residual(feats), planes out
    gemm_pl3<128, 128, 2, true ><<<dim3(128, 1, BVI), 256, GSMEM3>>>(
        dwh, dwl, wm2h, wm2l, merge_b2, feats, m2h, m2l, nullptr);
    // fwd GRU linear: planes in, fp32 hg out
    gemm_pl3<128, 256, 0, false><<<dim3(128, 2, BVI), 256, GSMEM3>>>(
        m2h, m2l, wgh, wgl, nullptr, nullptr, nullptr, nullptr, hg);
    gru_scan4<true ><<<dim3(16, CDIM, NB), 256>>>(hg, nullptr, g1h, g1l);
    // bwd GRU linear (H-flips cancel -> forward scan): planes in, fp32 hg out
    gemm_pl3<128, 256, 0, false><<<dim3(128, 2, BVI), 256, GSMEM3>>>(
        g1h, g1l, wgbh, wgbl, nullptr, nullptr, nullptr, nullptr, hg);
    gru_scan4<false><<<dim3(16, CDIM, NB), 256>>>(hg, bufB, nullptr, nullptr);
    // alpha conv + softmax pool (fp32 in, planes out)
    alpha_conv2<<<dim3(32, 1, BVI), 256>>>(bufB, alpha_w, alpha_b, alp);
    pool_k4pl<<<dim3(16, 1, NB), 256>>>(bufB, alp, plh, pll);
    // up: planes in, fp32 out
    gemm_pl3<128, 128, 0, false><<<dim3(128, 1, NB), 256, GSMEM3>>>(
        plh, pll, wuph, wupl, up_b, nullptr, nullptr, nullptr, u);
    // pixel shuffle + outc 3x3
    outc_k<<<dim3(1024, 3, NB), 256>>>(u, outc_w, outc_b, (float*)d_out);
}

// round 17
// speedup vs baseline: 1.0340x; 1.0340x over previous
#include <cuda_runtime.h>
#include <cuda_bf16.h>
#include <math.h>
#include <stdint.h>

#define NPIX 16384
#define CDIM 128
#define NB 2
#define NV 6
#define BVI 12
#define WW 128

typedef uint16_t u16;
typedef uint32_t u32;

// ---------------- scratch ----------------
__device__ float g_bufB[(size_t)BVI * CDIM * NPIX];     // g2 (fp32)
__device__ float g_hg  [(size_t)BVI * 2 * CDIM * NPIX]; // GRU linear out (fp32)
__device__ float g_alp [(size_t)BVI * NPIX];
__device__ float g_u   [(size_t)NB * CDIM * NPIX];
// single bf16 planes (attenuated path)
__device__ __align__(16) u16 g_m1 [(size_t)BVI * CDIM * NPIX];  // merge1 out
__device__ __align__(16) u16 g_dw [(size_t)BVI * CDIM * NPIX];  // dw out
// hi/lo bf16 planes (sensitive path)
__device__ __align__(16) u16 g_m2h[(size_t)BVI * CDIM * NPIX], g_m2l[(size_t)BVI * CDIM * NPIX];
__device__ __align__(16) u16 g_g1h[(size_t)BVI * CDIM * NPIX], g_g1l[(size_t)BVI * CDIM * NPIX];
__device__ __align__(16) u16 g_plh[(size_t)NB * CDIM * NPIX],  g_pll[(size_t)NB * CDIM * NPIX];
// weight hi/lo planes (k-major rows)
__device__ __align__(16) u16 g_wm1h[128 * 256], g_wm1l[128 * 256];
__device__ __align__(16) u16 g_wm2h[128 * 128], g_wm2l[128 * 128];
__device__ __align__(16) u16 g_wgh [256 * 128], g_wgl [256 * 128];
__device__ __align__(16) u16 g_wgbh[256 * 128], g_wgbl[256 * 128];
__device__ __align__(16) u16 g_wuph[128 * 128], g_wupl[128 * 128];

__device__ __forceinline__ float gelu_exact(float x) {
    return 0.5f * x * (1.0f + erff(x * 0.70710678118654752f));
}
__device__ __forceinline__ u32 smem_u32(const void* p) {
    return (u32)__cvta_generic_to_shared(p);
}
__device__ __forceinline__ void split_pack(float v0, float v1, u32& hi, u32& lo) {
    asm("cvt.rn.bf16x2.f32 %0, %1, %2;" : "=r"(hi) : "f"(v1), "f"(v0));
    float r0 = v0 - __uint_as_float(hi << 16);
    float r1 = v1 - __uint_as_float(hi & 0xffff0000u);
    asm("cvt.rn.bf16x2.f32 %0, %1, %2;" : "=r"(lo) : "f"(r1), "f"(r0));
}
__device__ __forceinline__ u32 pack_bf2(float v0, float v1) {
    u32 r;
    asm("cvt.rn.bf16x2.f32 %0, %1, %2;" : "=r"(r) : "f"(v1), "f"(v0));
    return r;
}
__device__ __forceinline__ float bf1(u16 w) { return __uint_as_float((u32)w << 16); }
__device__ __forceinline__ void ldm_x4(u32* r, u32 addr) {
    asm volatile("ldmatrix.sync.aligned.m8n8.x4.shared.b16 {%0,%1,%2,%3}, [%4];"
                 : "=r"(r[0]), "=r"(r[1]), "=r"(r[2]), "=r"(r[3]) : "r"(addr));
}
__device__ __forceinline__ void ldm_x4t(u32* r, u32 addr) {
    asm volatile("ldmatrix.sync.aligned.m8n8.x4.trans.shared.b16 {%0,%1,%2,%3}, [%4];"
                 : "=r"(r[0]), "=r"(r[1]), "=r"(r[2]), "=r"(r[3]) : "r"(addr));
}
__device__ __forceinline__ void mma_bf16(float* d, const u32* a, const u32* b) {
    asm volatile(
        "mma.sync.aligned.m16n8k16.row.col.f32.bf16.bf16.f32 "
        "{%0,%1,%2,%3}, {%4,%5,%6,%7}, {%8,%9}, {%0,%1,%2,%3};"
        : "+f"(d[0]), "+f"(d[1]), "+f"(d[2]), "+f"(d[3])
        : "r"(a[0]), "r"(a[1]), "r"(a[2]), "r"(a[3]), "r"(b[0]), "r"(b[1]));
}
__device__ __forceinline__ void cpasync16(u32 dst, const void* src) {
    asm volatile("cp.async.cg.shared.global [%0], [%1], 16;" :: "r"(dst), "l"(src));
}
__device__ __forceinline__ void cp_commit() {
    asm volatile("cp.async.commit_group;" ::: "memory");
}

// ---------------- tile constants ----------------
constexpr int KC = 32;
// streamed-A path (merge1)
constexpr int A_PITCH_B = 80;
constexpr int A_PLANE_B = 128 * A_PITCH_B;       // 10240
constexpr int A_STAGE_B = 2 * A_PLANE_B;         // 20480
constexpr int BB_PITCH = 272;
constexpr int BB_PLANE = KC * BB_PITCH;          // 8704
constexpr int BB_STAGE = 2 * BB_PLANE;           // 17408
constexpr int OFF_B0 = 2 * A_STAGE_B;            // 40960
constexpr int GSMEM  = OFF_B0 + 2 * BB_STAGE;    // 75776
// resident-A path
constexpr int AR_PITCH = 272;
constexpr int AR_PLANE = 128 * AR_PITCH;         // 34816
constexpr int R_OFF_B0 = 2 * AR_PLANE;           // 69632
constexpr int GSMEM_R1 = R_OFF_B0 + 2 * BB_PLANE; // 87040  (single-plane B)
constexpr int GSMEM_R2 = R_OFF_B0 + 2 * BB_STAGE; // 104448 (hi/lo B)

// ================= GEMM-F32IN (merge1): fp32 B, 3-pass; single-plane bf16 out ========
template <int KTOT, int MTOT, bool SPLIT>
__global__ __launch_bounds__(256, 2) void gemm_mma(
    const float* __restrict__ X0, const float* __restrict__ X1,
    const u16* __restrict__ Wh_g, const u16* __restrict__ Wl_g,
    const float* __restrict__ Bias, u16* __restrict__ OutP)
{
    extern __shared__ __align__(16) char sm[];
    const u32 sm0 = smem_u32(sm);

    const int img = blockIdx.z;
    const int p0  = blockIdx.x * 128;
    const int m0  = blockIdx.y * 128;
    const int tid = threadIdx.x;
    const int lane = tid & 31, wid = tid >> 5;
    const int wm = wid >> 2, wn = wid & 3;

    float acc[4][4][4];
#pragma unroll
    for (int i = 0; i < 4; i++)
#pragma unroll
        for (int j = 0; j < 4; j++)
#pragma unroll
            for (int q = 0; q < 4; q++) acc[i][j][q] = 0.f;

    constexpr int NCH = KTOT / KC;
    float4 breg[2][4];

    auto ldgB = [&](int c, int buf) {
        const int kbase = c * KC;
        const float* Xc = X0;
        int kb = kbase;
        if (SPLIT && kbase >= 128) { Xc = X1; kb = kbase - 128; }
        const size_t bbase = ((size_t)img * (SPLIT ? 128 : KTOT) + kb) * NPIX + p0;
#pragma unroll
        for (int i = 0; i < 4; i++) {
            int idx = tid + i * 256;
            int row = idx >> 5, seg = idx & 31;
            breg[buf][i] = *reinterpret_cast<const float4*>(
                Xc + bbase + (size_t)row * NPIX + seg * 4);
        }
    };
    auto copyA = [&](int c, int s) {
        const size_t abase = (size_t)m0 * KTOT + c * KC;
        const u32 adst = sm0 + s * A_STAGE_B;
#pragma unroll
        for (int i = 0; i < 4; i++) {
            int idx = tid + i * 256;
            int plane = idx >> 9, rem = idx & 511;
            int row = rem >> 2, seg = rem & 3;
            const u16* src = (plane ? Wl_g : Wh_g) + abase + (size_t)row * KTOT + seg * 8;
            cpasync16(adst + plane * A_PLANE_B + row * A_PITCH_B + seg * 16, src);
        }
    };

    const int lr  = lane & 7;
    const int lth = (lane >> 3) & 1;
    const int ltv = lane >> 4;
    const u32 a_row = (u32)(wm * 64 + lth * 8 + lr);

    ldgB(0, 0);
    copyA(0, 0); cp_commit();

#pragma unroll 1
    for (int c = 0; c < NCH; c++) {
        const int s = c & 1;
        if (c + 1 < NCH) ldgB(c + 1, s ^ 1);

        {
            const u32 bhoff = OFF_B0 + s * BB_STAGE;
#pragma unroll
            for (int i = 0; i < 4; i++) {
                int idx = tid + i * 256;
                int row = idx >> 5, seg = idx & 31;
                float4 v = breg[s][i];
                u32 h0, l0, h1, l1;
                split_pack(v.x, v.y, h0, l0);
                split_pack(v.z, v.w, h1, l1);
                u32 off = (u32)row * BB_PITCH + seg * 8;
                *reinterpret_cast<uint2*>(sm + bhoff + off) = make_uint2(h0, h1);
                *reinterpret_cast<uint2*>(sm + bhoff + BB_PLANE + off) = make_uint2(l0, l1);
            }
        }
        asm volatile("cp.async.wait_group 0;" ::: "memory");
        __syncthreads();

        if (c + 1 < NCH) { copyA(c + 1, s ^ 1); cp_commit(); }

        const u32 ah = sm0 + s * A_STAGE_B;
        const u32 al = ah + A_PLANE_B;
        const u32 bh = sm0 + OFF_B0 + s * BB_STAGE;
        const u32 bl = bh + BB_PLANE;

#pragma unroll
        for (int kk = 0; kk < KC / 16; kk++) {
            u32 af[4][4];
            u32 bfh[4][2], bfl[4][2];
            const u32 a_off = a_row * A_PITCH_B + kk * 32 + ltv * 16;
            const u32 b_off = (u32)(kk * 16 + lth * 8 + lr) * BB_PITCH + wn * 64 + ltv * 16;
#pragma unroll
            for (int mf = 0; mf < 4; mf++)
                ldm_x4(af[mf], ah + a_off + mf * 16 * A_PITCH_B);
#pragma unroll
            for (int nh = 0; nh < 2; nh++) {
                u32 r[4];
                ldm_x4t(r, bh + b_off + nh * 32);
                bfh[nh * 2][0] = r[0]; bfh[nh * 2][1] = r[1];
                bfh[nh * 2 + 1][0] = r[2]; bfh[nh * 2 + 1][1] = r[3];
            }
#pragma unroll
            for (int mf = 0; mf < 4; mf++)
#pragma unroll
                for (int nf = 0; nf < 4; nf++)
                    mma_bf16(acc[mf][nf], af[mf], bfh[nf]);
#pragma unroll
            for (int nh = 0; nh < 2; nh++) {
                u32 r[4];
                ldm_x4t(r, bl + b_off + nh * 32);
                bfl[nh * 2][0] = r[0]; bfl[nh * 2][1] = r[1];
                bfl[nh * 2 + 1][0] = r[2]; bfl[nh * 2 + 1][1] = r[3];
            }
#pragma unroll
            for (int mf = 0; mf < 4; mf++)
#pragma unroll
                for (int nf = 0; nf < 4; nf++)
                    mma_bf16(acc[mf][nf], af[mf], bfl[nf]);
#pragma unroll
            for (int mf = 0; mf < 4; mf++)
                ldm_x4(af[mf], al + a_off + mf * 16 * A_PITCH_B);
#pragma unroll
            for (int mf = 0; mf < 4; mf++)
#pragma unroll
                for (int nf = 0; nf < 4; nf++)
                    mma_bf16(acc[mf][nf], af[mf], bfh[nf]);
        }
    }

    const int g = lane >> 2, tg = lane & 3;
#pragma unroll
    for (int mf = 0; mf < 4; mf++) {
#pragma unroll
        for (int half = 0; half < 2; half++) {
            const int m = m0 + wm * 64 + mf * 16 + half * 8 + g;
            const float bias = Bias[m];
            const size_t rowb = ((size_t)img * MTOT + m) * NPIX;
#pragma unroll
            for (int nf = 0; nf < 4; nf++) {
                const int px = p0 + wn * 32 + nf * 8 + 2 * tg;
                float v0 = gelu_exact(acc[mf][nf][half * 2 + 0] + bias);
                float v1 = gelu_exact(acc[mf][nf][half * 2 + 1] + bias);
                reinterpret_cast<u32*>(OutP)[(rowb + px) >> 1] = pack_bf2(v0, v1);
            }
        }
    }
}

// ================= GEMM-PL1 (merge2): single-plane B, 2-pass, resident A ==========
// bias + fp32 residual; writes hi/lo planes.
__global__ __launch_bounds__(256, 2) void gemm_pl1(
    const u16* __restrict__ B_g,
    const u16* __restrict__ Wh_g, const u16* __restrict__ Wl_g,
    const float* __restrict__ Bias, const float* __restrict__ Res,
    u16* __restrict__ OutH, u16* __restrict__ OutL)
{
    extern __shared__ __align__(16) char sm[];
    const u32 sm0 = smem_u32(sm);

    const int img = blockIdx.z;
    const int p0  = blockIdx.x * 128;
    const int m0  = blockIdx.y * 128;
    const int tid = threadIdx.x;
    const int lane = tid & 31, wid = tid >> 5;
    const int wm = wid >> 2, wn = wid & 3;

    float acc[4][4][4];
#pragma unroll
    for (int i = 0; i < 4; i++)
#pragma unroll
        for (int j = 0; j < 4; j++)
#pragma unroll
            for (int q = 0; q < 4; q++) acc[i][j][q] = 0.f;

    {
        const size_t abase = (size_t)m0 * 128;
#pragma unroll
        for (int i = 0; i < 16; i++) {
            int idx = tid + i * 256;
            int plane = idx >> 11, rem = idx & 2047;
            int row = rem >> 4, seg = rem & 15;
            const u16* src = (plane ? Wl_g : Wh_g) + abase + (size_t)row * 128 + seg * 8;
            cpasync16(sm0 + plane * AR_PLANE + row * AR_PITCH + seg * 16, src);
        }
        cp_commit();
    }

    auto copyB = [&](int c, int s) {
        const size_t bbase = ((size_t)img * 128 + c * KC) * NPIX + p0;
#pragma unroll
        for (int i = 0; i < 2; i++) {
            int idx = tid + i * 256;
            int row = idx >> 4, seg = idx & 15;
            cpasync16(sm0 + R_OFF_B0 + s * BB_PLANE + row * BB_PITCH + seg * 16,
                      B_g + bbase + (size_t)row * NPIX + seg * 8);
        }
    };

    const int lr  = lane & 7;
    const int lth = (lane >> 3) & 1;
    const int ltv = lane >> 4;
    const u32 a_row = (u32)(wm * 64 + lth * 8 + lr);

    copyB(0, 0); cp_commit();

#pragma unroll 1
    for (int c = 0; c < 4; c++) {
        const int s = c & 1;
        asm volatile("cp.async.wait_group 0;" ::: "memory");
        __syncthreads();
        if (c + 1 < 4) { copyB(c + 1, s ^ 1); cp_commit(); }

        const u32 ah = sm0, al = sm0 + AR_PLANE;
        const u32 bb = sm0 + R_OFF_B0 + s * BB_PLANE;

#pragma unroll
        for (int kk = 0; kk < KC / 16; kk++) {
            u32 af[4][4];
            u32 bf[4][2];
            const u32 a_off = a_row * AR_PITCH + (c * KC + kk * 16) * 2 + ltv * 16;
            const u32 b_off = (u32)(kk * 16 + lth * 8 + lr) * BB_PITCH + wn * 64 + ltv * 16;
#pragma unroll
            for (int nh = 0; nh < 2; nh++) {
                u32 r[4];
                ldm_x4t(r, bb + b_off + nh * 32);
                bf[nh * 2][0] = r[0]; bf[nh * 2][1] = r[1];
                bf[nh * 2 + 1][0] = r[2]; bf[nh * 2 + 1][1] = r[3];
            }
#pragma unroll
            for (int mf = 0; mf < 4; mf++)
                ldm_x4(af[mf], ah + a_off + mf * 16 * AR_PITCH);
#pragma unroll
            for (int mf = 0; mf < 4; mf++)
#pragma unroll
                for (int nf = 0; nf < 4; nf++)
                    mma_bf16(acc[mf][nf], af[mf], bf[nf]);
#pragma unroll
            for (int mf = 0; mf < 4; mf++)
                ldm_x4(af[mf], al + a_off + mf * 16 * AR_PITCH);
#pragma unroll
            for (int mf = 0; mf < 4; mf++)
#pragma unroll
                for (int nf = 0; nf < 4; nf++)
                    mma_bf16(acc[mf][nf], af[mf], bf[nf]);
        }
    }

    const int g = lane >> 2, tg = lane & 3;
#pragma unroll
    for (int mf = 0; mf < 4; mf++) {
#pragma unroll
        for (int half = 0; half < 2; half++) {
            const int m = m0 + wm * 64 + mf * 16 + half * 8 + g;
            const float bias = Bias[m];
            const size_t rowb = ((size_t)img * 128 + m) * NPIX;
            const float* resrow = &Res[((size_t)img * CDIM + m) * NPIX];
#pragma unroll
            for (int nf = 0; nf < 4; nf++) {
                const int px = p0 + wn * 32 + nf * 8 + 2 * tg;
                float v0 = acc[mf][nf][half * 2 + 0] + bias + resrow[px];
                float v1 = acc[mf][nf][half * 2 + 1] + bias + resrow[px + 1];
                u32 hi, lo;
                split_pack(v0, v1, hi, lo);
                const size_t hw = (rowb + px) >> 1;
                reinterpret_cast<u32*>(OutH)[hw] = hi;
                reinterpret_cast<u32*>(OutL)[hw] = lo;
            }
        }
    }
}

// ================= GEMM-PL2 (GRU / up): hi/lo B, 3-pass, resident A ==========
template <int MTOT>
__global__ __launch_bounds__(256, 2) void gemm_pl2(
    const u16* __restrict__ Bh_g, const u16* __restrict__ Bl_g,
    const u16* __restrict__ Wh_g, const u16* __restrict__ Wl_g,
    const float* __restrict__ Bias, float* __restrict__ OutF)
{
    extern __shared__ __align__(16) char sm[];
    const u32 sm0 = smem_u32(sm);

    const int img = blockIdx.z;
    const int p0  = blockIdx.x * 128;
    const int m0  = blockIdx.y * 128;
    const int tid = threadIdx.x;
    const int lane = tid & 31, wid = tid >> 5;
    const int wm = wid >> 2, wn = wid & 3;

    float acc[4][4][4];
#pragma unroll
    for (int i = 0; i < 4; i++)
#pragma unroll
        for (int j = 0; j < 4; j++)
#pragma unroll
            for (int q = 0; q < 4; q++) acc[i][j][q] = 0.f;

    {
        const size_t abase = (size_t)m0 * 128;
#pragma unroll
        for (int i = 0; i < 16; i++) {
            int idx = tid + i * 256;
            int plane = idx >> 11, rem = idx & 2047;
            int row = rem >> 4, seg = rem & 15;
            const u16* src = (plane ? Wl_g : Wh_g) + abase + (size_t)row * 128 + seg * 8;
            cpasync16(sm0 + plane * AR_PLANE + row * AR_PITCH + seg * 16, src);
        }
        cp_commit();
    }

    auto copyB = [&](int c, int s) {
        const size_t bbase = ((size_t)img * 128 + c * KC) * NPIX + p0;
#pragma unroll
        for (int i = 0; i < 4; i++) {
            int idx = tid + i * 256;
            int plane = idx >> 9, rem = idx & 511;
            int row = rem >> 4, seg = rem & 15;
            const u16* src = (plane ? Bl_g : Bh_g) + bbase + (size_t)row * NPIX + seg * 8;
            cpasync16(sm0 + R_OFF_B0 + s * BB_STAGE + plane * BB_PLANE
                      + row * BB_PITCH + seg * 16, src);
        }
    };

    const int lr  = lane & 7;
    const int lth = (lane >> 3) & 1;
    const int ltv = lane >> 4;
    const u32 a_row = (u32)(wm * 64 + lth * 8 + lr);

    copyB(0, 0); cp_commit();

#pragma unroll 1
    for (int c = 0; c < 4; c++) {
        const int s = c & 1;
        asm volatile("cp.async.wait_group 0;" ::: "memory");
        __syncthreads();
        if (c + 1 < 4) { copyB(c + 1, s ^ 1); cp_commit(); }

        const u32 ah = sm0, al = sm0 + AR_PLANE;
        const u32 bh = sm0 + R_OFF_B0 + s * BB_STAGE;
        const u32 bl = bh + BB_PLANE;

#pragma unroll
        for (int kk = 0; kk < KC / 16; kk++) {
            u32 af[4][4];
            u32 bfh[4][2], bfl[4][2];
            const u32 a_off = a_row * AR_PITCH + (c * KC + kk * 16) * 2 + ltv * 16;
            const u32 b_off = (u32)(kk * 16 + lth * 8 + lr) * BB_PITCH + wn * 64 + ltv * 16;
#pragma unroll
            for (int nh = 0; nh < 2; nh++) {
                u32 r[4];
                ldm_x4t(r, bh + b_off + nh * 32);
                bfh[nh * 2][0] = r[0]; bfh[nh * 2][1] = r[1];
                bfh[nh * 2 + 1][0] = r[2]; bfh[nh * 2 + 1][1] = r[3];
            }
#pragma unroll
            for (int mf = 0; mf < 4; mf++)
                ldm_x4(af[mf], ah + a_off + mf * 16 * AR_PITCH);
#pragma unroll
            for (int mf = 0; mf < 4; mf++)
#pragma unroll
                for (int nf = 0; nf < 4; nf++)
                    mma_bf16(acc[mf][nf], af[mf], bfh[nf]);
#pragma unroll
            for (int nh = 0; nh < 2; nh++) {
                u32 r[4];
                ldm_x4t(r, bl + b_off + nh * 32);
                bfl[nh * 2][0] = r[0]; bfl[nh * 2][1] = r[1];
                bfl[nh * 2 + 1][0] = r[2]; bfl[nh * 2 + 1][1] = r[3];
            }
#pragma unroll
            for (int mf = 0; mf < 4; mf++)
#pragma unroll
                for (int nf = 0; nf < 4; nf++)
                    mma_bf16(acc[mf][nf], af[mf], bfl[nf]);
#pragma unroll
            for (int mf = 0; mf < 4; mf++)
                ldm_x4(af[mf], al + a_off + mf * 16 * AR_PITCH);
#pragma unroll
            for (int mf = 0; mf < 4; mf++)
#pragma unroll
                for (int nf = 0; nf < 4; nf++)
                    mma_bf16(acc[mf][nf], af[mf], bfh[nf]);
        }
    }

    const int g = lane >> 2, tg = lane & 3;
#pragma unroll
    for (int mf = 0; mf < 4; mf++) {
#pragma unroll
        for (int half = 0; half < 2; half++) {
            const int m = m0 + wm * 64 + mf * 16 + half * 8 + g;
            const float bias = Bias ? Bias[m] : 0.f;
            const size_t rowb = ((size_t)img * MTOT + m) * NPIX;
#pragma unroll
            for (int nf = 0; nf < 4; nf++) {
                const int px = p0 + wn * 32 + nf * 8 + 2 * tg;
                float v0 = acc[mf][nf][half * 2 + 0] + bias;
                float v1 = acc[mf][nf][half * 2 + 1] + bias;
                *reinterpret_cast<float2*>(&OutF[rowb + px]) = make_float2(v0, v1);
            }
        }
    }
}

// ---------------- fused weight prep ----------------
__global__ void prep_w_all(
    const float* __restrict__ w1, const float* __restrict__ w2,
    const float* __restrict__ wg, const float* __restrict__ wgb,
    const float* __restrict__ wup,
    u16* __restrict__ w1h, u16* __restrict__ w1l,
    u16* __restrict__ w2h, u16* __restrict__ w2l,
    u16* __restrict__ wgh, u16* __restrict__ wgl,
    u16* __restrict__ wgbh, u16* __restrict__ wgbl,
    u16* __restrict__ wuph, u16* __restrict__ wupl)
{
    int i = blockIdx.x * 256 + threadIdx.x;
    const float* src; u16 *dh, *dl; int off;
    if      (i < 32768)  { src = w1;  dh = w1h;  dl = w1l;  off = i; }
    else if (i < 49152)  { src = w2;  dh = w2h;  dl = w2l;  off = i - 32768; }
    else if (i < 81920)  { src = wg;  dh = wgh;  dl = wgl;  off = i - 49152; }
    else if (i < 114688) { src = wgb; dh = wgbh; dl = wgbl; off = i - 81920; }
    else                 { src = wup; dh = wuph; dl = wupl; off = i - 114688; }
    float v = src[off];
    float hf = __bfloat162float(__float2bfloat16(v));
    dh[off] = (u16)(__float_as_uint(hf) >> 16);
    dl[off] = (u16)(__float_as_uint(__bfloat162float(__float2bfloat16(v - hf))) >> 16);
}

// ---------------- depthwise 3x3 + bias + GELU: bf16 plane in, bf16 plane out ---------
__global__ __launch_bounds__(256) void dw3x3_pp(
    const u16* __restrict__ inP, const float* __restrict__ wd,
    const float* __restrict__ bd, u16* __restrict__ outP)
{
    int c = blockIdx.y, img = blockIdx.z;
    int pix0 = (blockIdx.x * 256 + threadIdx.x) * 2;
    int h = pix0 >> 7, w0 = pix0 & 127;
    const size_t base = ((size_t)img * CDIM + c) * NPIX;
    const u16* p = inP + base;
    float wreg[9];
#pragma unroll
    for (int i = 0; i < 9; i++) wreg[i] = wd[c * 9 + i];
    float s0 = bd[c], s1 = bd[c];
#pragma unroll
    for (int ky = 0; ky < 3; ky++) {
        int hh = h + ky - 1;
        if ((unsigned)hh >= 128u) continue;
        float v0 = (w0 - 1 >= 0)   ? bf1(p[hh * WW + w0 - 1]) : 0.f;
        float v1 = bf1(p[hh * WW + w0]);
        float v2 = bf1(p[hh * WW + w0 + 1]);
        float v3 = (w0 + 2 < 128)  ? bf1(p[hh * WW + w0 + 2]) : 0.f;
        s0 = fmaf(wreg[ky * 3 + 0], v0, s0);
        s0 = fmaf(wreg[ky * 3 + 1], v1, s0);
        s0 = fmaf(wreg[ky * 3 + 2], v2, s0);
        s1 = fmaf(wreg[ky * 3 + 0], v1, s1);
        s1 = fmaf(wreg[ky * 3 + 1], v2, s1);
        s1 = fmaf(wreg[ky * 3 + 2], v3, s1);
    }
    reinterpret_cast<u32*>(outP)[(base + pix0) >> 1] =
        pack_bf2(gelu_exact(s0), gelu_exact(s1));
}

// ---------------- minGRU scan (fp32 in, prefetched); OUTPL: hi/lo planes else fp32 ----
template <bool OUTPL>
__global__ __launch_bounds__(256) void gru_scan4(
    const float* __restrict__ hg, float* __restrict__ gF,
    u16* __restrict__ gH, u16* __restrict__ gL)
{
    int c = blockIdx.y, b = blockIdx.z;
    int pix0 = (blockIdx.x * 256 + threadIdx.x) * 4;
    float4 hid[NV], gt[NV];
#pragma unroll
    for (int v = 0; v < NV; v++) {
        size_t base = (((size_t)(b * NV + v)) * 2 * CDIM + c) * NPIX + pix0;
        hid[v] = *reinterpret_cast<const float4*>(&hg[base]);
        gt[v]  = *reinterpret_cast<const float4*>(&hg[base + (size_t)CDIM * NPIX]);
    }
    float4 h = make_float4(0.f, 0.f, 0.f, 0.f);
#pragma unroll
    for (int v = 0; v < NV; v++) {
        float z, ht;
        z = 1.f / (1.f + expf(-gt[v].x));
        ht = (hid[v].x >= 0.f) ? (hid[v].x + 0.5f) : (1.f / (1.f + expf(-hid[v].x)));
        h.x = (1.f - z) * h.x + z * ht;
        z = 1.f / (1.f + expf(-gt[v].y));
        ht = (hid[v].y >= 0.f) ? (hid[v].y + 0.5f) : (1.f / (1.f + expf(-hid[v].y)));
        h.y = (1.f - z) * h.y + z * ht;
        z = 1.f / (1.f + expf(-gt[v].z));
        ht = (hid[v].z >= 0.f) ? (hid[v].z + 0.5f) : (1.f / (1.f + expf(-hid[v].z)));
        h.z = (1.f - z) * h.z + z * ht;
        z = 1.f / (1.f + expf(-gt[v].w));
        ht = (hid[v].w >= 0.f) ? (hid[v].w + 0.5f) : (1.f / (1.f + expf(-hid[v].w)));
        h.w = (1.f - z) * h.w + z * ht;
        size_t d = (((size_t)(b * NV + v)) * CDIM + c) * NPIX + pix0;
        if (OUTPL) {
            u32 h0, l0, h1, l1;
            split_pack(h.x, h.y, h0, l0);
            split_pack(h.z, h.w, h1, l1);
            *reinterpret_cast<uint2*>(&gH[d]) = make_uint2(h0, h1);
            *reinterpret_cast<uint2*>(&gL[d]) = make_uint2(l0, l1);
        } else {
            *reinterpret_cast<float4*>(&gF[d]) = h;
        }
    }
}

// ---------------- alpha: 3x3 conv C->1, 2 px/thread ----------------
__global__ __launch_bounds__(256) void alpha_conv2(
    const float* __restrict__ g2, const float* __restrict__ aw,
    const float* __restrict__ ab, float* __restrict__ alpha)
{
    __shared__ float w[1152];
    for (int i = threadIdx.x; i < 1152; i += 256) w[i] = aw[i];
    __syncthreads();
    int img = blockIdx.z;
    int pix0 = (blockIdx.x * 256 + threadIdx.x) * 2;
    int h = pix0 >> 7, x0 = pix0 & 127;
    float s0 = ab[0], s1 = ab[0];
    const float* base = g2 + (size_t)img * CDIM * NPIX;
    for (int c = 0; c < CDIM; c++) {
        const float* p  = base + (size_t)c * NPIX;
        const float* wc = w + c * 9;
#pragma unroll
        for (int ky = 0; ky < 3; ky++) {
            int hh = h + ky - 1;
            if ((unsigned)hh >= 128u) continue;
            float v0 = (x0 - 1 >= 0)  ? p[hh * WW + x0 - 1] : 0.f;
            float v1 = p[hh * WW + x0];
            float v2 = p[hh * WW + x0 + 1];
            float v3 = (x0 + 2 < 128) ? p[hh * WW + x0 + 2] : 0.f;
            s0 = fmaf(wc[ky * 3 + 0], v0, s0);
            s0 = fmaf(wc[ky * 3 + 1], v1, s0);
            s0 = fmaf(wc[ky * 3 + 2], v2, s0);
            s1 = fmaf(wc[ky * 3 + 0], v1, s1);
            s1 = fmaf(wc[ky * 3 + 1], v2, s1);
            s1 = fmaf(wc[ky * 3 + 2], v3, s1);
        }
    }
    *reinterpret_cast<float2*>(&alpha[(size_t)img * NPIX + pix0]) = make_float2(s0, s1);
}

// ---------------- softmax pool (fp32 in, hi/lo planes out) ----------------
__global__ __launch_bounds__(256) void pool_k4pl(
    const float* __restrict__ g2, const float* __restrict__ alpha,
    u16* __restrict__ outH, u16* __restrict__ outL)
{
    int b = blockIdx.z;
    int pix0 = (blockIdx.x * 256 + threadIdx.x) * 4;
    float4 a[NV];
    float4 mx = make_float4(-1e30f, -1e30f, -1e30f, -1e30f);
#pragma unroll
    for (int v = 0; v < NV; v++) {
        a[v] = *reinterpret_cast<const float4*>(&alpha[(size_t)(b * NV + v) * NPIX + pix0]);
        mx.x = fmaxf(mx.x, a[v].x); mx.y = fmaxf(mx.y, a[v].y);
        mx.z = fmaxf(mx.z, a[v].z); mx.w = fmaxf(mx.w, a[v].w);
    }
    float4 sum = make_float4(0.f, 0.f, 0.f, 0.f);
#pragma unroll
    for (int v = 0; v < NV; v++) {
        a[v].x = expf(a[v].x - mx.x); sum.x += a[v].x;
        a[v].y = expf(a[v].y - mx.y); sum.y += a[v].y;
        a[v].z = expf(a[v].z - mx.z); sum.z += a[v].z;
        a[v].w = expf(a[v].w - mx.w); sum.w += a[v].w;
    }
    float4 inv = make_float4(1.f / sum.x, 1.f / sum.y, 1.f / sum.z, 1.f / sum.w);
#pragma unroll
    for (int v = 0; v < NV; v++) {
        a[v].x *= inv.x; a[v].y *= inv.y; a[v].z *= inv.z; a[v].w *= inv.w;
    }
    for (int c = 0; c < CDIM; c++) {
        float4 s = make_float4(0.f, 0.f, 0.f, 0.f);
#pragma unroll
        for (int v = 0; v < NV; v++) {
            float4 gv = *reinterpret_cast<const float4*>(
                &g2[(((size_t)(b * NV + v)) * CDIM + c) * NPIX + pix0]);
            s.x = fmaf(a[v].x, gv.x, s.x);
            s.y = fmaf(a[v].y, gv.y, s.y);
            s.z = fmaf(a[v].z, gv.z, s.z);
            s.w = fmaf(a[v].w, gv.w, s.w);
        }
        size_t d = ((size_t)b * CDIM + c) * NPIX + pix0;
        u32 h0, l0, h1, l1;
        split_pack(s.x, s.y, h0, l0);
        split_pack(s.z, s.w, h1, l1);
        *reinterpret_cast<uint2*>(&outH[d]) = make_uint2(h0, h1);
        *reinterpret_cast<uint2*>(&outL[d]) = make_uint2(l0, l1);
    }
}

// ---------------- pixel-shuffle(4) + 3x3 conv 8->3 (512->512 resize = identity) --------
__global__ __launch_bounds__(256) void outc_k(
    const float* __restrict__ u, const float* __restrict__ wt,
    const float* __restrict__ bs, float* __restrict__ out)
{
    __shared__ float w[216];
    if (threadIdx.x < 216) w[threadIdx.x] = wt[threadIdx.x];
    __syncthreads();
    int b = blockIdx.z, co = blockIdx.y;
    int idx = blockIdx.x * 256 + threadIdx.x;
    int y = idx >> 9, x = idx & 511;
    float s = bs[co];
    const float* ub = u + (size_t)b * CDIM * NPIX;
#pragma unroll
    for (int ky = 0; ky < 3; ky++) {
        int yy = y + ky - 1;
        if ((unsigned)yy >= 512u) continue;
        int sy = yy & 3, hy = yy >> 2;
#pragma unroll
        for (int kx = 0; kx < 3; kx++) {
            int xx = x + kx - 1;
            if ((unsigned)xx >= 512u) continue;
            int sx = xx & 3, hx = xx >> 2;
            const float* up = ub + (size_t)(sy * 4 + sx) * NPIX + hy * WW + hx;
#pragma unroll
            for (int ci = 0; ci < 8; ci++)
                s = fmaf(w[(co * 8 + ci) * 9 + ky * 3 + kx], up[(size_t)ci * 16 * NPIX], s);
        }
    }
    out[((size_t)b * 3 + co) * (512 * 512) + idx] = s;
}

// ---------------- launch ----------------
extern "C" void kernel_launch(void* const* d_in, const int* in_sizes, int n_in,
                              void* d_out, int out_size)
{
    const float* feats     = (const float*)d_in[0];
    const float* prj       = (const float*)d_in[1];
    const float* merge_w1  = (const float*)d_in[2];
    const float* merge_b1  = (const float*)d_in[3];
    const float* merge_wd  = (const float*)d_in[4];
    const float* merge_bd  = (const float*)d_in[5];
    const float* merge_w2  = (const float*)d_in[6];
    const float* merge_b2  = (const float*)d_in[7];
    const float* gru_w     = (const float*)d_in[8];
    const float* gru_bw    = (const float*)d_in[9];
    const float* alpha_w   = (const float*)d_in[10];
    const float* alpha_b   = (const float*)d_in[11];
    const float* up_w      = (const float*)d_in[12];
    const float* up_b      = (const float*)d_in[13];
    const float* outc_w    = (const float*)d_in[14];
    const float* outc_b    = (const float*)d_in[15];

    float *bufB, *hg, *alp, *u;
    u16 *m1p, *dwp, *m2h, *m2l, *g1h, *g1l, *plh, *pll;
    u16 *wm1h, *wm1l, *wm2h, *wm2l, *wgh, *wgl, *wgbh, *wgbl, *wuph, *wupl;
    cudaGetSymbolAddress((void**)&bufB, g_bufB);
    cudaGetSymbolAddress((void**)&hg,   g_hg);
    cudaGetSymbolAddress((void**)&alp,  g_alp);
    cudaGetSymbolAddress((void**)&u,    g_u);
    cudaGetSymbolAddress((void**)&m1p,  g_m1);
    cudaGetSymbolAddress((void**)&dwp,  g_dw);
    cudaGetSymbolAddress((void**)&m2h,  g_m2h);  cudaGetSymbolAddress((void**)&m2l,  g_m2l);
    cudaGetSymbolAddress((void**)&g1h,  g_g1h);  cudaGetSymbolAddress((void**)&g1l,  g_g1l);
    cudaGetSymbolAddress((void**)&plh,  g_plh);  cudaGetSymbolAddress((void**)&pll,  g_pll);
    cudaGetSymbolAddress((void**)&wm1h, g_wm1h); cudaGetSymbolAddress((void**)&wm1l, g_wm1l);
    cudaGetSymbolAddress((void**)&wm2h, g_wm2h); cudaGetSymbolAddress((void**)&wm2l, g_wm2l);
    cudaGetSymbolAddress((void**)&wgh,  g_wgh);  cudaGetSymbolAddress((void**)&wgl,  g_wgl);
    cudaGetSymbolAddress((void**)&wgbh, g_wgbh); cudaGetSymbolAddress((void**)&wgbl, g_wgbl);
    cudaGetSymbolAddress((void**)&wuph, g_wuph); cudaGetSymbolAddress((void**)&wupl, g_wupl);

    cudaFuncSetAttribute(gemm_mma<256, 128, true>, cudaFuncAttributeMaxDynamicSharedMemorySize, GSMEM);
    cudaFuncSetAttribute(gemm_pl1, cudaFuncAttributeMaxDynamicSharedMemorySize, GSMEM_R1);
    cudaFuncSetAttribute(gemm_pl2<256>, cudaFuncAttributeMaxDynamicSharedMemorySize, GSMEM_R2);
    cudaFuncSetAttribute(gemm_pl2<128>, cudaFuncAttributeMaxDynamicSharedMemorySize, GSMEM_R2);

    prep_w_all<<<512, 256>>>(merge_w1, merge_w2, gru_w, gru_bw, up_w,
                             wm1h, wm1l, wm2h, wm2l, wgh, wgl, wgbh, wgbl, wuph, wupl);

    // merge1: 1x1 (2C->C) + GELU -> single bf16 plane (attenuated path)
    gemm_mma<256, 128, true><<<dim3(128, 1, BVI), 256, GSMEM>>>(
        feats, prj, wm1h, wm1l, merge_b1, m1p);
    // depthwise 3x3 + GELU: plane in -> plane out
    dw3x3_pp<<<dim3(32, CDIM, BVI), 256>>>(m1p, merge_wd, merge_bd, dwp);
    // merge2: single-plane B, bias + fp32 residual(feats) -> hi/lo planes (exact path)
    gemm_pl1<<<dim3(128, 1, BVI), 256, GSMEM_R1>>>(
        dwp, wm2h, wm2l, merge_b2, feats, m2h, m2l);
    // fwd GRU linear: hi/lo in, fp32 hg out
    gemm_pl2<256><<<dim3(128, 2, BVI), 256, GSMEM_R2>>>(
        m2h, m2l, wgh, wgl, nullptr, hg);
    gru_scan4<true ><<<dim3(16, CDIM, NB), 256>>>(hg, nullptr, g1h, g1l);
    // bwd GRU linear (H-flips cancel -> forward scan)
    gemm_pl2<256><<<dim3(128, 2, BVI), 256, GSMEM_R2>>>(
        g1h, g1l, wgbh, wgbl, nullptr, hg);
    gru_scan4<false><<<dim3(16, CDIM, NB), 256>>>(hg, bufB, nullptr, nullptr);
    // alpha conv + softmax pool (fp32 in, hi/lo planes out)
    alpha_conv2<<<dim3(32, 1, BVI), 256>>>(bufB, alpha_w, alpha_b, alp);
    pool_k4pl<<<dim3(16, 1, NB), 256>>>(bufB, alp, plh, pll);
    // up: hi/lo in, fp32 out
    gemm_pl2<128><<<dim3(128, 1, NB), 256, GSMEM_R2>>>(
        plh, pll, wuph, wupl, up_b, u);
    // pixel shuffle + outc 3x3
    outc_k<<<dim3(1024, 3, NB), 256>>>(u, outc_w, outc_b, (float*)d_out);
}